// round 12
// baseline (speedup 1.0000x reference)
#include <cuda_runtime.h>
#include <cuda_fp16.h>
#include <math.h>
#include <stdint.h>

#define N_TOK 8192
#define DM    1024
#define DFF   4096
#define NE    8
#define TOPK  2
#define CAP   1280
#define SROWB 144         // smem row stride bytes (128 data + 16 pad)
#define SSTAGE 55296      // gemm13 stage bytes (384 rows x 144B)
#define SSTAGE2 36864     // gemm2 stage bytes (256 rows x 144B)
#define NSTAGE 4

// ---------------- scratch ----------------
__device__ __half g_buf[2 * NE * CAP * DM];
__device__ __half g_h  [2 * NE * CAP * DFF];
__device__ __half g_w1t[NE * DFF * DM];
__device__ __half g_w3t[NE * DFF * DM];
__device__ __half g_w2t[NE * DM * DFF];
__device__ float  g_probs[N_TOK * NE];
__device__ int    g_top_idx[N_TOK * TOPK];
__device__ float  g_top_w [N_TOK * TOPK];
__device__ int    g_pos   [N_TOK * TOPK];
__device__ int    g_inv   [2 * NE * CAP];     // (k,e,pos) -> token
__device__ int    g_cnt   [TOPK * NE];

// ---------------- helpers ----------------
__device__ __forceinline__ uint32_t smem_u32(const void* p) {
    uint32_t a;
    asm("{ .reg .u64 t; cvta.to.shared.u64 t, %1; cvt.u32.u64 %0, t; }" : "=r"(a) : "l"(p));
    return a;
}
__device__ __forceinline__ void mma_f16(float* c, const uint32_t* a, uint32_t b0, uint32_t b1) {
    asm volatile(
        "mma.sync.aligned.m16n8k16.row.col.f32.f16.f16.f32 "
        "{%0,%1,%2,%3}, {%4,%5,%6,%7}, {%8,%9}, {%0,%1,%2,%3};"
        : "+f"(c[0]), "+f"(c[1]), "+f"(c[2]), "+f"(c[3])
        : "r"(a[0]), "r"(a[1]), "r"(a[2]), "r"(a[3]), "r"(b0), "r"(b1));
}
__device__ __forceinline__ void ldsm_x4(uint32_t& r0, uint32_t& r1, uint32_t& r2, uint32_t& r3,
                                        uint32_t addr) {
    asm volatile("ldmatrix.sync.aligned.m8n8.x4.shared.b16 {%0,%1,%2,%3}, [%4];"
                 : "=r"(r0), "=r"(r1), "=r"(r2), "=r"(r3) : "r"(addr));
}
__device__ __forceinline__ void cp16(uint32_t s, const void* g) {
    asm volatile("cp.async.cg.shared.global [%0], [%1], 16;" :: "r"(s), "l"(g) : "memory");
}
#define CP_COMMIT() asm volatile("cp.async.commit_group;" ::: "memory")
#define CP_WAIT2()  asm volatile("cp.async.wait_group 2;" ::: "memory")

__device__ __forceinline__ uint32_t h2bits(float a, float b) {
    __half2 h = __floats2half2_rn(a, b);
    return *(uint32_t*)&h;
}

// ---------------- 0a. weight convert (fp32 -> fp16) ----------------
__global__ __launch_bounds__(256) void cvt_kernel(const float4* __restrict__ src,
                                                  uint2* __restrict__ dst, int n4) {
    int i = blockIdx.x * blockDim.x + threadIdx.x;
    if (i < n4) {
        float4 v = src[i];
        uint2 o;
        o.x = h2bits(v.x, v.y);
        o.y = h2bits(v.z, v.w);
        dst[i] = o;
    }
}

// ---------------- 0b. zero d_out (poisoned by harness; atomic epilogue accumulates) ----------------
__global__ __launch_bounds__(256) void zero_kernel(float4* __restrict__ out) {
    out[(size_t)blockIdx.x * 256 + threadIdx.x] = make_float4(0.f, 0.f, 0.f, 0.f);
}

// ---------------- 1. router ----------------
__global__ __launch_bounds__(256) void router_kernel(const float* __restrict__ x,
                                                     const float* __restrict__ gw) {
    int warp = (blockIdx.x * blockDim.x + threadIdx.x) >> 5;
    int lane = threadIdx.x & 31;
    if (warp >= N_TOK) return;
    const float* xr = x + (size_t)warp * DM;
    float acc[NE];
#pragma unroll
    for (int e = 0; e < NE; e++) acc[e] = 0.f;
    for (int i = lane; i < DM; i += 32) {
        float xv = xr[i];
#pragma unroll
        for (int e = 0; e < NE; e++) acc[e] += xv * gw[e * DM + i];
    }
#pragma unroll
    for (int off = 16; off > 0; off >>= 1)
#pragma unroll
        for (int e = 0; e < NE; e++) acc[e] += __shfl_xor_sync(0xffffffffu, acc[e], off);
    if (lane == 0) {
        float mx = acc[0];
#pragma unroll
        for (int e = 1; e < NE; e++) mx = fmaxf(mx, acc[e]);
        float p[NE], s = 0.f;
#pragma unroll
        for (int e = 0; e < NE; e++) { p[e] = expf(acc[e] - mx); s += p[e]; }
        float inv = 1.f / s;
        int i0 = 0;
#pragma unroll
        for (int e = 1; e < NE; e++) if (p[e] > p[i0]) i0 = e;
        int i1 = (i0 == 0) ? 1 : 0;
#pragma unroll
        for (int e = 0; e < NE; e++) if (e != i0 && e != i1 && p[e] > p[i1]) i1 = e;
#pragma unroll
        for (int e = 0; e < NE; e++) g_probs[warp * NE + e] = p[e] * inv;
        float p0 = p[i0] * inv, p1 = p[i1] * inv;
        float ws = p0 + p1 + 1e-10f;
        g_top_idx[warp * 2 + 0] = i0;  g_top_w[warp * 2 + 0] = p0 / ws;
        g_top_idx[warp * 2 + 1] = i1;  g_top_w[warp * 2 + 1] = p1 / ws;
    }
}

// ---------------- 2. capacity scan ----------------
__global__ __launch_bounds__(256) void scan_kernel() {
    int k = blockIdx.x;
    int t = threadIdx.x;
    const int CH = N_TOK / 256;
    __shared__ int cnt[256][NE];
    int local[NE];
#pragma unroll
    for (int e = 0; e < NE; e++) local[e] = 0;
    for (int i = 0; i < CH; i++) local[g_top_idx[(t * CH + i) * 2 + k]]++;
#pragma unroll
    for (int e = 0; e < NE; e++) cnt[t][e] = local[e];
    __syncthreads();
    if (t < NE) {
        int run = 0;
        for (int i = 0; i < 256; i++) { int v = cnt[i][t]; cnt[i][t] = run; run += v; }
        g_cnt[k * NE + t] = run;
    }
    __syncthreads();
    int off[NE];
#pragma unroll
    for (int e = 0; e < NE; e++) off[e] = cnt[t][e];
    for (int i = 0; i < CH; i++) {
        int tk = (t * CH + i) * 2 + k;
        g_pos[tk] = off[g_top_idx[tk]]++;
    }
}

// ---------------- 3. gather (fp32 -> fp16, + inverse map) ----------------
__global__ __launch_bounds__(256) void gather_kernel(const float* __restrict__ x) {
    int tk = blockIdx.x;
    int pos = g_pos[tk];
    if (pos >= CAP) return;
    int e = g_top_idx[tk];
    int k = tk & 1, t = tk >> 1;
    float4 v = ((const float4*)(x + (size_t)t * DM))[threadIdx.x];
    uint2 o;
    o.x = h2bits(v.x, v.y);
    o.y = h2bits(v.z, v.w);
    uint2* dst = (uint2*)(g_buf + ((size_t)(k * NE + e) * CAP + pos) * DM);
    dst[threadIdx.x] = o;
    if (threadIdx.x == 0) g_inv[(k * NE + e) * CAP + pos] = t;
}

// ---------------- 4. gemm13 fp16 + ldmatrix (unchanged winner) ----------------
__global__ __launch_bounds__(256) void gemm13_mma(const __half* __restrict__ W1,
                                                  const __half* __restrict__ W3) {
    int z = blockIdx.z, e = z & (NE - 1);
    int rows = g_cnt[z]; if (rows > CAP) rows = CAP;
    int m0 = blockIdx.y * 128; if (m0 >= rows) return;
    int n0 = blockIdx.x * 128;

    extern __shared__ char dsm[];
    uint32_t sb = smem_u32(dsm);

    const char* gA  = (const char*)(g_buf + (size_t)z * CAP * DM + (size_t)m0 * DM);
    const char* gB1 = (const char*)(W1 + (size_t)e * DFF * DM + (size_t)n0 * DM);
    const char* gB3 = (const char*)(W3 + (size_t)e * DFF * DM + (size_t)n0 * DM);
    const int GR = DM * 2;

    int tid = threadIdx.x, wid = tid >> 5, lane = tid & 31;
    int wm = wid >> 2, wn = wid & 3;
    int g = lane >> 2, tg = lane & 3;

    uint32_t Aoff = (uint32_t)((wm * 64 + ((lane >> 3) & 1) * 8 + (lane & 7)) * SROWB
                               + (lane >> 4) * 16);
    uint32_t Boff = (uint32_t)(((lane >> 4) * 8 + (lane & 7)) * SROWB
                               + ((lane >> 3) & 1) * 16);

    auto issue = [&](int c) {
        uint32_t st = sb + (uint32_t)(c % NSTAGE) * SSTAGE;
        int kb = c * 128;
#pragma unroll
        for (int i = 0; i < 4; i++) {
            int f = tid + i * 256, r = f >> 3, c4 = f & 7;
            cp16(st + r * SROWB + c4 * 16, gA + (size_t)r * GR + kb + c4 * 16);
        }
#pragma unroll
        for (int i = 0; i < 4; i++) {
            int f = tid + i * 256, r = f >> 3, c4 = f & 7;
            cp16(st + 18432u + r * SROWB + c4 * 16, gB1 + (size_t)r * GR + kb + c4 * 16);
        }
#pragma unroll
        for (int i = 0; i < 4; i++) {
            int f = tid + i * 256, r = f >> 3, c4 = f & 7;
            cp16(st + 36864u + r * SROWB + c4 * 16, gB3 + (size_t)r * GR + kb + c4 * 16);
        }
    };

    float acc1[4][4][4], acc2[4][4][4];
#pragma unroll
    for (int mi = 0; mi < 4; mi++)
#pragma unroll
        for (int ni = 0; ni < 4; ni++)
#pragma unroll
            for (int r = 0; r < 4; r++) { acc1[mi][ni][r] = 0.f; acc2[mi][ni][r] = 0.f; }

    uint32_t af[2][4][4], b1f[2][4][2], b3f[2][4][2];

    auto loadfrag = [&](uint32_t stu, int kk, int buf) {
        uint32_t ka = stu + (uint32_t)(kk * 32);
#pragma unroll
        for (int mi = 0; mi < 4; mi++)
            ldsm_x4(af[buf][mi][0], af[buf][mi][1], af[buf][mi][2], af[buf][mi][3],
                    ka + Aoff + (uint32_t)(mi * 16 * SROWB));
#pragma unroll
        for (int np = 0; np < 2; np++) {
            uint32_t nboff = (uint32_t)((wn * 32 + np * 16) * SROWB);
            ldsm_x4(b1f[buf][2*np][0], b1f[buf][2*np][1], b1f[buf][2*np+1][0], b1f[buf][2*np+1][1],
                    ka + 18432u + Boff + nboff);
            ldsm_x4(b3f[buf][2*np][0], b3f[buf][2*np][1], b3f[buf][2*np+1][0], b3f[buf][2*np+1][1],
                    ka + 36864u + Boff + nboff);
        }
    };

    const int NC = DM / 64;   // 16
    issue(0); CP_COMMIT();
    issue(1); CP_COMMIT();
    issue(2); CP_COMMIT();

    for (int c = 0; c < NC; c++) {
        CP_WAIT2();
        __syncthreads();
        if (c + 3 < NC) issue(c + 3);
        CP_COMMIT();
        uint32_t stu = sb + (uint32_t)(c % NSTAGE) * SSTAGE;
        loadfrag(stu, 0, 0);
#pragma unroll
        for (int kk = 0; kk < 4; kk++) {
            int cur = kk & 1;
            if (kk < 3) loadfrag(stu, kk + 1, cur ^ 1);
#pragma unroll
            for (int ni = 0; ni < 4; ni++) {
#pragma unroll
                for (int mi = 0; mi < 4; mi++)
                    mma_f16(acc1[mi][ni], af[cur][mi], b1f[cur][ni][0], b1f[cur][ni][1]);
#pragma unroll
                for (int mi = 0; mi < 4; mi++)
                    mma_f16(acc2[mi][ni], af[cur][mi], b3f[cur][ni][0], b3f[cur][ni][1]);
            }
        }
    }

    __half* H = g_h + (size_t)z * CAP * DFF;
#pragma unroll
    for (int mi = 0; mi < 4; mi++)
#pragma unroll
        for (int half = 0; half < 2; half++) {
            int m = m0 + wm * 64 + mi * 16 + half * 8 + g;
            if (m < rows) {
#pragma unroll
                for (int ni = 0; ni < 4; ni++) {
                    float v0 = acc1[mi][ni][half * 2 + 0];
                    float v1 = acc1[mi][ni][half * 2 + 1];
                    float o0 = (v0 / (1.f + expf(-v0))) * acc2[mi][ni][half * 2 + 0];
                    float o1 = (v1 / (1.f + expf(-v1))) * acc2[mi][ni][half * 2 + 1];
                    int col = n0 + wn * 32 + ni * 8 + 2 * tg;
                    __half2 hv = __floats2half2_rn(o0, o1);
                    *(__half2*)&H[(size_t)m * DFF + col] = hv;
                }
            }
        }
}

// ---------------- 5. gemm2 fp16: 128M x 128N, warp 64x32, fused atomic combine ----------------
__global__ __launch_bounds__(256) void gemm2_mma(const __half* __restrict__ W2,
                                                 float* __restrict__ out) {
    int z = blockIdx.z, e = z & (NE - 1);
    int kidx = z >> 3;
    int rows = g_cnt[z]; if (rows > CAP) rows = CAP;
    int m0 = blockIdx.y * 128; if (m0 >= rows) return;
    int n0 = blockIdx.x * 128;

    extern __shared__ char dsm[];
    uint32_t sb = smem_u32(dsm);

    const char* gA = (const char*)(g_h + (size_t)z * CAP * DFF + (size_t)m0 * DFF);
    const char* gB = (const char*)(W2 + (size_t)e * DM * DFF + (size_t)n0 * DFF);
    const int GR = DFF * 2;

    int tid = threadIdx.x, wid = tid >> 5, lane = tid & 31;
    int wm = wid >> 2, wn = wid & 3;
    int g = lane >> 2, tg = lane & 3;

    uint32_t Aoff = (uint32_t)((wm * 64 + ((lane >> 3) & 1) * 8 + (lane & 7)) * SROWB
                               + (lane >> 4) * 16);
    uint32_t Boff = (uint32_t)(((lane >> 4) * 8 + (lane & 7)) * SROWB
                               + ((lane >> 3) & 1) * 16);

    auto issue = [&](int c) {
        uint32_t st = sb + (uint32_t)(c % NSTAGE) * SSTAGE2;
        int kb = c * 128;
#pragma unroll
        for (int i = 0; i < 4; i++) {
            int f = tid + i * 256, r = f >> 3, c4 = f & 7;
            cp16(st + r * SROWB + c4 * 16, gA + (size_t)r * GR + kb + c4 * 16);
        }
#pragma unroll
        for (int i = 0; i < 4; i++) {
            int f = tid + i * 256, r = f >> 3, c4 = f & 7;
            cp16(st + 18432u + r * SROWB + c4 * 16, gB + (size_t)r * GR + kb + c4 * 16);
        }
    };

    float acc[4][4][4];
#pragma unroll
    for (int mi = 0; mi < 4; mi++)
#pragma unroll
        for (int ni = 0; ni < 4; ni++)
#pragma unroll
            for (int r = 0; r < 4; r++) acc[mi][ni][r] = 0.f;

    uint32_t af[2][4][4], bf[2][4][2];

    auto loadfrag = [&](uint32_t stu, int kk, int buf) {
        uint32_t ka = stu + (uint32_t)(kk * 32);
#pragma unroll
        for (int mi = 0; mi < 4; mi++)
            ldsm_x4(af[buf][mi][0], af[buf][mi][1], af[buf][mi][2], af[buf][mi][3],
                    ka + Aoff + (uint32_t)(mi * 16 * SROWB));
#pragma unroll
        for (int np = 0; np < 2; np++) {
            uint32_t nboff = (uint32_t)((wn * 32 + np * 16) * SROWB);
            ldsm_x4(bf[buf][2*np][0], bf[buf][2*np][1], bf[buf][2*np+1][0], bf[buf][2*np+1][1],
                    ka + 18432u + Boff + nboff);
        }
    };

    const int NC = DFF / 64;  // 64
    issue(0); CP_COMMIT();
    issue(1); CP_COMMIT();
    issue(2); CP_COMMIT();

    for (int c = 0; c < NC; c++) {
        CP_WAIT2();
        __syncthreads();
        if (c + 3 < NC) issue(c + 3);
        CP_COMMIT();
        uint32_t stu = sb + (uint32_t)(c % NSTAGE) * SSTAGE2;
        loadfrag(stu, 0, 0);
#pragma unroll
        for (int kk = 0; kk < 4; kk++) {
            int cur = kk & 1;
            if (kk < 3) loadfrag(stu, kk + 1, cur ^ 1);
#pragma unroll
            for (int ni = 0; ni < 4; ni++)
#pragma unroll
                for (int mi = 0; mi < 4; mi++)
                    mma_f16(acc[mi][ni], af[cur][mi], bf[cur][ni][0], bf[cur][ni][1]);
        }
    }

    // fused combine: out[token] += top_w * val (exactly 2 contributions per element;
    // two-operand fp add is commutative -> replay-deterministic)
#pragma unroll
    for (int mi = 0; mi < 4; mi++)
#pragma unroll
        for (int half = 0; half < 2; half++) {
            int m = m0 + wm * 64 + mi * 16 + half * 8 + g;
            if (m < rows) {
                int t = g_inv[z * CAP + m];
                float w = g_top_w[t * 2 + kidx];
                float* orow = out + (size_t)t * DM;
#pragma unroll
                for (int ni = 0; ni < 4; ni++) {
                    int col = n0 + wn * 32 + ni * 8 + 2 * tg;
                    atomicAdd(&orow[col],     w * acc[mi][ni][half * 2 + 0]);
                    atomicAdd(&orow[col + 1], w * acc[mi][ni][half * 2 + 1]);
                }
            }
        }
}

// ---------------- 7. aux loss ----------------
__global__ __launch_bounds__(256) void aux_kernel(float* __restrict__ out, int out_size) {
    __shared__ float red[256];
    __shared__ float Ps[NE];
    int tid = threadIdx.x;
    float loc[NE];
#pragma unroll
    for (int e = 0; e < NE; e++) loc[e] = 0.f;
    for (int i = tid; i < N_TOK; i += 256) {
#pragma unroll
        for (int e = 0; e < NE; e++) loc[e] += g_probs[i * NE + e];
    }
    for (int e = 0; e < NE; e++) {
        red[tid] = loc[e];
        __syncthreads();
        for (int s = 128; s > 0; s >>= 1) {
            if (tid < s) red[tid] += red[tid + s];
            __syncthreads();
        }
        if (tid == 0) Ps[e] = red[0];
        __syncthreads();
    }
    if (tid == 0) {
        float aux = 0.f;
        for (int e = 0; e < NE; e++) {
            float f = (float)(g_cnt[e] + g_cnt[NE + e]) / (float)(N_TOK * TOPK);
            float P = Ps[e] / (float)N_TOK;
            aux += f * P;
        }
        out[out_size - 1] = aux * (float)NE;
    }
}

// ---------------- launch ----------------
extern "C" void kernel_launch(void* const* d_in, const int* in_sizes, int n_in,
                              void* d_out, int out_size) {
    const float* x  = (const float*)d_in[0];
    const float* gw = (const float*)d_in[1];
    const float* w1 = (const float*)d_in[2];
    const float* w2 = (const float*)d_in[3];
    const float* w3 = (const float*)d_in[4];
    float* out = (float*)d_out;

    const int SMEM  = NSTAGE * SSTAGE;    // 221184
    const int SMEM2 = NSTAGE * SSTAGE2;   // 147456
    cudaFuncSetAttribute(gemm13_mma, cudaFuncAttributeMaxDynamicSharedMemorySize, SMEM);
    cudaFuncSetAttribute(gemm2_mma,  cudaFuncAttributeMaxDynamicSharedMemorySize, SMEM2);

    __half* w1t; cudaGetSymbolAddress((void**)&w1t, g_w1t);
    __half* w3t; cudaGetSymbolAddress((void**)&w3t, g_w3t);
    __half* w2t; cudaGetSymbolAddress((void**)&w2t, g_w2t);

    const int N4 = NE * DFF * DM / 4;
    const int CVT_GRID = (N4 + 255) / 256;

    cudaStream_t s2 = 0;
    cudaEvent_t evA = 0, evB = 0, evC = 0;
    bool ok =
        cudaStreamCreateWithFlags(&s2, cudaStreamNonBlocking) == cudaSuccess &&
        cudaEventCreateWithFlags(&evA, cudaEventDisableTiming) == cudaSuccess &&
        cudaEventCreateWithFlags(&evB, cudaEventDisableTiming) == cudaSuccess &&
        cudaEventCreateWithFlags(&evC, cudaEventDisableTiming) == cudaSuccess;
    // objects intentionally leaked (destroying during active capture is illegal;
    // kernel_launch runs only a handful of times).

    if (ok) {
        cudaEventRecord(evA, 0);
        cudaStreamWaitEvent(s2, evA, 0);

        cvt_kernel<<<CVT_GRID, 256, 0, s2>>>((const float4*)w1, (uint2*)w1t, N4);
        cvt_kernel<<<CVT_GRID, 256, 0, s2>>>((const float4*)w3, (uint2*)w3t, N4);
        cudaEventRecord(evB, s2);
        cvt_kernel<<<CVT_GRID, 256, 0, s2>>>((const float4*)w2, (uint2*)w2t, N4);
        cudaEventRecord(evC, s2);

        zero_kernel<<<N_TOK * DM / 1024, 256>>>((float4*)out);
        router_kernel<<<N_TOK / 8, 256>>>(x, gw);
        scan_kernel<<<2, 256>>>();
        gather_kernel<<<N_TOK * TOPK, 256>>>(x);

        cudaStreamWaitEvent(0, evB, 0);
        dim3 g1(DFF / 128, CAP / 128, TOPK * NE);
        gemm13_mma<<<g1, 256, SMEM>>>(w1t, w3t);

        cudaStreamWaitEvent(0, evC, 0);
        dim3 g2(DM / 128, CAP / 128, TOPK * NE);   // 8 x 10 x 16 = 1280 CTAs
        gemm2_mma<<<g2, 256, SMEM2>>>(w2t, out);

        aux_kernel<<<1, 256>>>(out, out_size);
    } else {
        cvt_kernel<<<CVT_GRID, 256>>>((const float4*)w1, (uint2*)w1t, N4);
        cvt_kernel<<<CVT_GRID, 256>>>((const float4*)w3, (uint2*)w3t, N4);
        cvt_kernel<<<CVT_GRID, 256>>>((const float4*)w2, (uint2*)w2t, N4);
        zero_kernel<<<N_TOK * DM / 1024, 256>>>((float4*)out);
        router_kernel<<<N_TOK / 8, 256>>>(x, gw);
        scan_kernel<<<2, 256>>>();
        gather_kernel<<<N_TOK * TOPK, 256>>>(x);
        dim3 g1(DFF / 128, CAP / 128, TOPK * NE);
        gemm13_mma<<<g1, 256, SMEM>>>(w1t, w3t);
        dim3 g2(DM / 128, CAP / 128, TOPK * NE);
        gemm2_mma<<<g2, 256, SMEM2>>>(w2t, out);
        aux_kernel<<<1, 256>>>(out, out_size);
    }
}

// round 13
// speedup vs baseline: 1.0767x; 1.0767x over previous
#include <cuda_runtime.h>
#include <cuda_fp16.h>
#include <math.h>
#include <stdint.h>

#define N_TOK 8192
#define DM    1024
#define DFF   4096
#define NE    8
#define TOPK  2
#define CAP   1280
#define SROWB 144         // smem row stride bytes (128 data + 16 pad)
#define SSTAGE 55296      // bytes per pipeline stage (384 rows x 144B)
#define NSTAGE 4

// ---------------- scratch ----------------
__device__ __half g_buf[2 * NE * CAP * DM];
__device__ __half g_h  [2 * NE * CAP * DFF];
__device__ __half g_ob [2 * NE * CAP * DM];        // fp16 expert outputs
__device__ __half g_w1t[NE * DFF * DM];
__device__ __half g_w3t[NE * DFF * DM];
__device__ __half g_w2t[NE * DM * DFF];
__device__ float  g_probs[N_TOK * NE];
__device__ int    g_top_idx[N_TOK * TOPK];
__device__ float  g_top_w [N_TOK * TOPK];
__device__ int    g_pos   [N_TOK * TOPK];
__device__ int    g_cnt   [TOPK * NE];

// ---------------- helpers ----------------
__device__ __forceinline__ uint32_t smem_u32(const void* p) {
    uint32_t a;
    asm("{ .reg .u64 t; cvta.to.shared.u64 t, %1; cvt.u32.u64 %0, t; }" : "=r"(a) : "l"(p));
    return a;
}
__device__ __forceinline__ void mma_f16(float* c, const uint32_t* a, uint32_t b0, uint32_t b1) {
    asm volatile(
        "mma.sync.aligned.m16n8k16.row.col.f32.f16.f16.f32 "
        "{%0,%1,%2,%3}, {%4,%5,%6,%7}, {%8,%9}, {%0,%1,%2,%3};"
        : "+f"(c[0]), "+f"(c[1]), "+f"(c[2]), "+f"(c[3])
        : "r"(a[0]), "r"(a[1]), "r"(a[2]), "r"(a[3]), "r"(b0), "r"(b1));
}
__device__ __forceinline__ void ldsm_x4(uint32_t& r0, uint32_t& r1, uint32_t& r2, uint32_t& r3,
                                        uint32_t addr) {
    asm volatile("ldmatrix.sync.aligned.m8n8.x4.shared.b16 {%0,%1,%2,%3}, [%4];"
                 : "=r"(r0), "=r"(r1), "=r"(r2), "=r"(r3) : "r"(addr));
}
__device__ __forceinline__ void cp16(uint32_t s, const void* g) {
    asm volatile("cp.async.cg.shared.global [%0], [%1], 16;" :: "r"(s), "l"(g) : "memory");
}
#define CP_COMMIT() asm volatile("cp.async.commit_group;" ::: "memory")
#define CP_WAIT2()  asm volatile("cp.async.wait_group 2;" ::: "memory")

__device__ __forceinline__ uint32_t h2bits(float a, float b) {
    __half2 h = __floats2half2_rn(a, b);
    return *(uint32_t*)&h;
}

// ---------------- 0. weight convert (fp32 -> fp16) ----------------
__global__ __launch_bounds__(256) void cvt_kernel(const float4* __restrict__ src,
                                                  uint2* __restrict__ dst, int n4) {
    int i = blockIdx.x * blockDim.x + threadIdx.x;
    if (i < n4) {
        float4 v = src[i];
        uint2 o;
        o.x = h2bits(v.x, v.y);
        o.y = h2bits(v.z, v.w);
        dst[i] = o;
    }
}

// ---------------- 1. router (float4-vectorized) ----------------
__global__ __launch_bounds__(256) void router_kernel(const float* __restrict__ x,
                                                     const float* __restrict__ gw) {
    int warp = (blockIdx.x * blockDim.x + threadIdx.x) >> 5;
    int lane = threadIdx.x & 31;
    if (warp >= N_TOK) return;
    const float4* xr = (const float4*)(x + (size_t)warp * DM);
    const float4* gw4 = (const float4*)gw;
    float acc[NE];
#pragma unroll
    for (int e = 0; e < NE; e++) acc[e] = 0.f;
#pragma unroll
    for (int i = 0; i < DM / 4 / 32; i++) {         // 8 iterations
        int idx = i * 32 + lane;
        float4 xv = xr[idx];
#pragma unroll
        for (int e = 0; e < NE; e++) {
            float4 wv = gw4[e * (DM / 4) + idx];
            acc[e] += xv.x * wv.x + xv.y * wv.y + xv.z * wv.z + xv.w * wv.w;
        }
    }
#pragma unroll
    for (int off = 16; off > 0; off >>= 1)
#pragma unroll
        for (int e = 0; e < NE; e++) acc[e] += __shfl_xor_sync(0xffffffffu, acc[e], off);
    if (lane == 0) {
        float mx = acc[0];
#pragma unroll
        for (int e = 1; e < NE; e++) mx = fmaxf(mx, acc[e]);
        float p[NE], s = 0.f;
#pragma unroll
        for (int e = 0; e < NE; e++) { p[e] = expf(acc[e] - mx); s += p[e]; }
        float inv = 1.f / s;
        int i0 = 0;
#pragma unroll
        for (int e = 1; e < NE; e++) if (p[e] > p[i0]) i0 = e;
        int i1 = (i0 == 0) ? 1 : 0;
#pragma unroll
        for (int e = 0; e < NE; e++) if (e != i0 && e != i1 && p[e] > p[i1]) i1 = e;
#pragma unroll
        for (int e = 0; e < NE; e++) g_probs[warp * NE + e] = p[e] * inv;
        float p0 = p[i0] * inv, p1 = p[i1] * inv;
        float ws = p0 + p1 + 1e-10f;
        g_top_idx[warp * 2 + 0] = i0;  g_top_w[warp * 2 + 0] = p0 / ws;
        g_top_idx[warp * 2 + 1] = i1;  g_top_w[warp * 2 + 1] = p1 / ws;
    }
}

// ---------------- 2. capacity scan ----------------
__global__ __launch_bounds__(256) void scan_kernel() {
    int k = blockIdx.x;
    int t = threadIdx.x;
    const int CH = N_TOK / 256;
    __shared__ int cnt[256][NE];
    int local[NE];
#pragma unroll
    for (int e = 0; e < NE; e++) local[e] = 0;
    for (int i = 0; i < CH; i++) local[g_top_idx[(t * CH + i) * 2 + k]]++;
#pragma unroll
    for (int e = 0; e < NE; e++) cnt[t][e] = local[e];
    __syncthreads();
    if (t < NE) {
        int run = 0;
        for (int i = 0; i < 256; i++) { int v = cnt[i][t]; cnt[i][t] = run; run += v; }
        g_cnt[k * NE + t] = run;
    }
    __syncthreads();
    int off[NE];
#pragma unroll
    for (int e = 0; e < NE; e++) off[e] = cnt[t][e];
    for (int i = 0; i < CH; i++) {
        int tk = (t * CH + i) * 2 + k;
        g_pos[tk] = off[g_top_idx[tk]]++;
    }
}

// ---------------- 3. gather (fp32 -> fp16 at write) ----------------
__global__ __launch_bounds__(256) void gather_kernel(const float* __restrict__ x) {
    int tk = blockIdx.x;
    int pos = g_pos[tk];
    if (pos >= CAP) return;
    int e = g_top_idx[tk];
    int k = tk & 1, t = tk >> 1;
    float4 v = ((const float4*)(x + (size_t)t * DM))[threadIdx.x];
    uint2 o;
    o.x = h2bits(v.x, v.y);
    o.y = h2bits(v.z, v.w);
    uint2* dst = (uint2*)(g_buf + ((size_t)(k * NE + e) * CAP + pos) * DM);
    dst[threadIdx.x] = o;
}

// ---------------- 4. gemm13 fp16 + ldmatrix (unchanged winner) ----------------
__global__ __launch_bounds__(256) void gemm13_mma(const __half* __restrict__ W1,
                                                  const __half* __restrict__ W3) {
    int z = blockIdx.z, e = z & (NE - 1);
    int rows = g_cnt[z]; if (rows > CAP) rows = CAP;
    int m0 = blockIdx.y * 128; if (m0 >= rows) return;
    int n0 = blockIdx.x * 128;

    extern __shared__ char dsm[];
    uint32_t sb = smem_u32(dsm);

    const char* gA  = (const char*)(g_buf + (size_t)z * CAP * DM + (size_t)m0 * DM);
    const char* gB1 = (const char*)(W1 + (size_t)e * DFF * DM + (size_t)n0 * DM);
    const char* gB3 = (const char*)(W3 + (size_t)e * DFF * DM + (size_t)n0 * DM);
    const int GR = DM * 2;

    int tid = threadIdx.x, wid = tid >> 5, lane = tid & 31;
    int wm = wid >> 2, wn = wid & 3;
    int g = lane >> 2, tg = lane & 3;

    uint32_t Aoff = (uint32_t)((wm * 64 + ((lane >> 3) & 1) * 8 + (lane & 7)) * SROWB
                               + (lane >> 4) * 16);
    uint32_t Boff = (uint32_t)(((lane >> 4) * 8 + (lane & 7)) * SROWB
                               + ((lane >> 3) & 1) * 16);

    auto issue = [&](int c) {
        uint32_t st = sb + (uint32_t)(c % NSTAGE) * SSTAGE;
        int kb = c * 128;
#pragma unroll
        for (int i = 0; i < 4; i++) {
            int f = tid + i * 256, r = f >> 3, c4 = f & 7;
            cp16(st + r * SROWB + c4 * 16, gA + (size_t)r * GR + kb + c4 * 16);
        }
#pragma unroll
        for (int i = 0; i < 4; i++) {
            int f = tid + i * 256, r = f >> 3, c4 = f & 7;
            cp16(st + 18432u + r * SROWB + c4 * 16, gB1 + (size_t)r * GR + kb + c4 * 16);
        }
#pragma unroll
        for (int i = 0; i < 4; i++) {
            int f = tid + i * 256, r = f >> 3, c4 = f & 7;
            cp16(st + 36864u + r * SROWB + c4 * 16, gB3 + (size_t)r * GR + kb + c4 * 16);
        }
    };

    float acc1[4][4][4], acc2[4][4][4];
#pragma unroll
    for (int mi = 0; mi < 4; mi++)
#pragma unroll
        for (int ni = 0; ni < 4; ni++)
#pragma unroll
            for (int r = 0; r < 4; r++) { acc1[mi][ni][r] = 0.f; acc2[mi][ni][r] = 0.f; }

    uint32_t af[2][4][4], b1f[2][4][2], b3f[2][4][2];

    auto loadfrag = [&](uint32_t stu, int kk, int buf) {
        uint32_t ka = stu + (uint32_t)(kk * 32);
#pragma unroll
        for (int mi = 0; mi < 4; mi++)
            ldsm_x4(af[buf][mi][0], af[buf][mi][1], af[buf][mi][2], af[buf][mi][3],
                    ka + Aoff + (uint32_t)(mi * 16 * SROWB));
#pragma unroll
        for (int np = 0; np < 2; np++) {
            uint32_t nboff = (uint32_t)((wn * 32 + np * 16) * SROWB);
            ldsm_x4(b1f[buf][2*np][0], b1f[buf][2*np][1], b1f[buf][2*np+1][0], b1f[buf][2*np+1][1],
                    ka + 18432u + Boff + nboff);
            ldsm_x4(b3f[buf][2*np][0], b3f[buf][2*np][1], b3f[buf][2*np+1][0], b3f[buf][2*np+1][1],
                    ka + 36864u + Boff + nboff);
        }
    };

    const int NC = DM / 64;   // 16
    issue(0); CP_COMMIT();
    issue(1); CP_COMMIT();
    issue(2); CP_COMMIT();

    for (int c = 0; c < NC; c++) {
        CP_WAIT2();
        __syncthreads();
        if (c + 3 < NC) issue(c + 3);
        CP_COMMIT();
        uint32_t stu = sb + (uint32_t)(c % NSTAGE) * SSTAGE;
        loadfrag(stu, 0, 0);
#pragma unroll
        for (int kk = 0; kk < 4; kk++) {
            int cur = kk & 1;
            if (kk < 3) loadfrag(stu, kk + 1, cur ^ 1);
#pragma unroll
            for (int ni = 0; ni < 4; ni++) {
#pragma unroll
                for (int mi = 0; mi < 4; mi++)
                    mma_f16(acc1[mi][ni], af[cur][mi], b1f[cur][ni][0], b1f[cur][ni][1]);
#pragma unroll
                for (int mi = 0; mi < 4; mi++)
                    mma_f16(acc2[mi][ni], af[cur][mi], b3f[cur][ni][0], b3f[cur][ni][1]);
            }
        }
    }

    __half* H = g_h + (size_t)z * CAP * DFF;
#pragma unroll
    for (int mi = 0; mi < 4; mi++)
#pragma unroll
        for (int half = 0; half < 2; half++) {
            int m = m0 + wm * 64 + mi * 16 + half * 8 + g;
            if (m < rows) {
#pragma unroll
                for (int ni = 0; ni < 4; ni++) {
                    float v0 = acc1[mi][ni][half * 2 + 0];
                    float v1 = acc1[mi][ni][half * 2 + 1];
                    float o0 = (v0 / (1.f + expf(-v0))) * acc2[mi][ni][half * 2 + 0];
                    float o1 = (v1 / (1.f + expf(-v1))) * acc2[mi][ni][half * 2 + 1];
                    int col = n0 + wn * 32 + ni * 8 + 2 * tg;
                    __half2 hv = __floats2half2_rn(o0, o1);
                    *(__half2*)&H[(size_t)m * DFF + col] = hv;
                }
            }
        }
}

// ---------------- 5. gemm2 fp16 + ldmatrix (fp16 output) ----------------
__global__ __launch_bounds__(256) void gemm2_mma(const __half* __restrict__ W2) {
    int z = blockIdx.z, e = z & (NE - 1);
    int rows = g_cnt[z]; if (rows > CAP) rows = CAP;
    int m0 = blockIdx.y * 128; if (m0 >= rows) return;
    int n0 = blockIdx.x * 256;

    extern __shared__ char dsm[];
    uint32_t sb = smem_u32(dsm);

    const char* gA = (const char*)(g_h + (size_t)z * CAP * DFF + (size_t)m0 * DFF);
    const char* gB = (const char*)(W2 + (size_t)e * DM * DFF + (size_t)n0 * DFF);
    const int GR = DFF * 2;

    int tid = threadIdx.x, wid = tid >> 5, lane = tid & 31;
    int wm = wid >> 2, wn = wid & 3;
    int g = lane >> 2, tg = lane & 3;

    uint32_t Aoff = (uint32_t)((wm * 64 + ((lane >> 3) & 1) * 8 + (lane & 7)) * SROWB
                               + (lane >> 4) * 16);
    uint32_t Boff = (uint32_t)(((lane >> 4) * 8 + (lane & 7)) * SROWB
                               + ((lane >> 3) & 1) * 16);

    auto issue = [&](int c) {
        uint32_t st = sb + (uint32_t)(c % NSTAGE) * SSTAGE;
        int kb = c * 128;
#pragma unroll
        for (int i = 0; i < 4; i++) {
            int f = tid + i * 256, r = f >> 3, c4 = f & 7;
            cp16(st + r * SROWB + c4 * 16, gA + (size_t)r * GR + kb + c4 * 16);
        }
#pragma unroll
        for (int i = 0; i < 8; i++) {
            int f = tid + i * 256, r = f >> 3, c4 = f & 7;
            cp16(st + 18432u + r * SROWB + c4 * 16, gB + (size_t)r * GR + kb + c4 * 16);
        }
    };

    float acc[4][8][4];
#pragma unroll
    for (int mi = 0; mi < 4; mi++)
#pragma unroll
        for (int ni = 0; ni < 8; ni++)
#pragma unroll
            for (int r = 0; r < 4; r++) acc[mi][ni][r] = 0.f;

    uint32_t af[2][4][4], bf[2][8][2];

    auto loadfrag = [&](uint32_t stu, int kk, int buf) {
        uint32_t ka = stu + (uint32_t)(kk * 32);
#pragma unroll
        for (int mi = 0; mi < 4; mi++)
            ldsm_x4(af[buf][mi][0], af[buf][mi][1], af[buf][mi][2], af[buf][mi][3],
                    ka + Aoff + (uint32_t)(mi * 16 * SROWB));
#pragma unroll
        for (int np = 0; np < 4; np++) {
            uint32_t nboff = (uint32_t)((wn * 64 + np * 16) * SROWB);
            ldsm_x4(bf[buf][2*np][0], bf[buf][2*np][1], bf[buf][2*np+1][0], bf[buf][2*np+1][1],
                    ka + 18432u + Boff + nboff);
        }
    };

    const int NC = DFF / 64;  // 64
    issue(0); CP_COMMIT();
    issue(1); CP_COMMIT();
    issue(2); CP_COMMIT();

    for (int c = 0; c < NC; c++) {
        CP_WAIT2();
        __syncthreads();
        if (c + 3 < NC) issue(c + 3);
        CP_COMMIT();
        uint32_t stu = sb + (uint32_t)(c % NSTAGE) * SSTAGE;
        loadfrag(stu, 0, 0);
#pragma unroll
        for (int kk = 0; kk < 4; kk++) {
            int cur = kk & 1;
            if (kk < 3) loadfrag(stu, kk + 1, cur ^ 1);
#pragma unroll
            for (int ni = 0; ni < 8; ni++)
#pragma unroll
                for (int mi = 0; mi < 4; mi++)
                    mma_f16(acc[mi][ni], af[cur][mi], bf[cur][ni][0], bf[cur][ni][1]);
        }
    }

    __half* O = g_ob + (size_t)z * CAP * DM;
#pragma unroll
    for (int mi = 0; mi < 4; mi++)
#pragma unroll
        for (int half = 0; half < 2; half++) {
            int m = m0 + wm * 64 + mi * 16 + half * 8 + g;
            if (m < rows) {
#pragma unroll
                for (int ni = 0; ni < 8; ni++) {
                    int col = n0 + wn * 64 + ni * 8 + 2 * tg;
                    __half2 hv = __floats2half2_rn(acc[mi][ni][half * 2 + 0],
                                                   acc[mi][ni][half * 2 + 1]);
                    *(__half2*)&O[(size_t)m * DM + col] = hv;
                }
            }
        }
}

// ---------------- 6. weighted scatter/combine (fp16 in, fp32 out) ----------------
__global__ __launch_bounds__(256) void scatter_kernel(float* __restrict__ out) {
    int t = blockIdx.x;
    int d4 = threadIdx.x;
    float4 acc = {0.f, 0.f, 0.f, 0.f};
#pragma unroll
    for (int k = 0; k < TOPK; k++) {
        int tk = t * 2 + k;
        int pos = g_pos[tk];
        if (pos < CAP) {
            int e = g_top_idx[tk];
            float w = g_top_w[tk];
            const __half2* src = (const __half2*)(g_ob + ((size_t)(k * NE + e) * CAP + pos) * DM);
            float2 v0 = __half22float2(src[d4 * 2 + 0]);
            float2 v1 = __half22float2(src[d4 * 2 + 1]);
            acc.x += v0.x * w; acc.y += v0.y * w; acc.z += v1.x * w; acc.w += v1.y * w;
        }
    }
    ((float4*)(out + (size_t)t * DM))[d4] = acc;
}

// ---------------- 7. aux loss ----------------
__global__ __launch_bounds__(256) void aux_kernel(float* __restrict__ out, int out_size) {
    __shared__ float red[256];
    __shared__ float Ps[NE];
    int tid = threadIdx.x;
    float loc[NE];
#pragma unroll
    for (int e = 0; e < NE; e++) loc[e] = 0.f;
    for (int i = tid; i < N_TOK; i += 256) {
#pragma unroll
        for (int e = 0; e < NE; e++) loc[e] += g_probs[i * NE + e];
    }
    for (int e = 0; e < NE; e++) {
        red[tid] = loc[e];
        __syncthreads();
        for (int s = 128; s > 0; s >>= 1) {
            if (tid < s) red[tid] += red[tid + s];
            __syncthreads();
        }
        if (tid == 0) Ps[e] = red[0];
        __syncthreads();
    }
    if (tid == 0) {
        float aux = 0.f;
        for (int e = 0; e < NE; e++) {
            float f = (float)(g_cnt[e] + g_cnt[NE + e]) / (float)(N_TOK * TOPK);
            float P = Ps[e] / (float)N_TOK;
            aux += f * P;
        }
        out[out_size - 1] = aux * (float)NE;
    }
}

// ---------------- launch ----------------
extern "C" void kernel_launch(void* const* d_in, const int* in_sizes, int n_in,
                              void* d_out, int out_size) {
    const float* x  = (const float*)d_in[0];
    const float* gw = (const float*)d_in[1];
    const float* w1 = (const float*)d_in[2];
    const float* w2 = (const float*)d_in[3];
    const float* w3 = (const float*)d_in[4];
    float* out = (float*)d_out;

    const int SMEM = NSTAGE * SSTAGE;   // 221184
    cudaFuncSetAttribute(gemm13_mma, cudaFuncAttributeMaxDynamicSharedMemorySize, SMEM);
    cudaFuncSetAttribute(gemm2_mma,  cudaFuncAttributeMaxDynamicSharedMemorySize, SMEM);

    __half* w1t; cudaGetSymbolAddress((void**)&w1t, g_w1t);
    __half* w3t; cudaGetSymbolAddress((void**)&w3t, g_w3t);
    __half* w2t; cudaGetSymbolAddress((void**)&w2t, g_w2t);

    const int N4 = NE * DFF * DM / 4;
    const int CVT_GRID = (N4 + 255) / 256;

    cudaStream_t s2 = 0;
    cudaEvent_t evA = 0, evB = 0, evC = 0;
    bool ok =
        cudaStreamCreateWithFlags(&s2, cudaStreamNonBlocking) == cudaSuccess &&
        cudaEventCreateWithFlags(&evA, cudaEventDisableTiming) == cudaSuccess &&
        cudaEventCreateWithFlags(&evB, cudaEventDisableTiming) == cudaSuccess &&
        cudaEventCreateWithFlags(&evC, cudaEventDisableTiming) == cudaSuccess;
    // objects intentionally leaked (destroying during active capture is illegal;
    // kernel_launch runs only a handful of times).

    if (ok) {
        cudaEventRecord(evA, 0);
        cudaStreamWaitEvent(s2, evA, 0);

        cvt_kernel<<<CVT_GRID, 256, 0, s2>>>((const float4*)w1, (uint2*)w1t, N4);
        cvt_kernel<<<CVT_GRID, 256, 0, s2>>>((const float4*)w3, (uint2*)w3t, N4);
        cudaEventRecord(evB, s2);
        cvt_kernel<<<CVT_GRID, 256, 0, s2>>>((const float4*)w2, (uint2*)w2t, N4);
        cudaEventRecord(evC, s2);

        router_kernel<<<N_TOK / 8, 256>>>(x, gw);
        scan_kernel<<<2, 256>>>();
        gather_kernel<<<N_TOK * TOPK, 256>>>(x);

        cudaStreamWaitEvent(0, evB, 0);
        dim3 g1(DFF / 128, CAP / 128, TOPK * NE);
        gemm13_mma<<<g1, 256, SMEM>>>(w1t, w3t);

        cudaStreamWaitEvent(0, evC, 0);
        dim3 g2(DM / 256, CAP / 128, TOPK * NE);
        gemm2_mma<<<g2, 256, SMEM>>>(w2t);

        scatter_kernel<<<N_TOK, 256>>>(out);
        aux_kernel<<<1, 256>>>(out, out_size);
    } else {
        cvt_kernel<<<CVT_GRID, 256>>>((const float4*)w1, (uint2*)w1t, N4);
        cvt_kernel<<<CVT_GRID, 256>>>((const float4*)w3, (uint2*)w3t, N4);
        cvt_kernel<<<CVT_GRID, 256>>>((const float4*)w2, (uint2*)w2t, N4);
        router_kernel<<<N_TOK / 8, 256>>>(x, gw);
        scan_kernel<<<2, 256>>>();
        gather_kernel<<<N_TOK * TOPK, 256>>>(x);
        dim3 g1(DFF / 128, CAP / 128, TOPK * NE);
        gemm13_mma<<<g1, 256, SMEM>>>(w1t, w3t);
        dim3 g2(DM / 256, CAP / 128, TOPK * NE);
        gemm2_mma<<<g2, 256, SMEM>>>(w2t);
        scatter_kernel<<<N_TOK, 256>>>(out);
        aux_kernel<<<1, 256>>>(out, out_size);
    }
}

// round 14
// speedup vs baseline: 1.0936x; 1.0157x over previous
#include <cuda_runtime.h>
#include <cuda_fp16.h>
#include <math.h>
#include <stdint.h>

#define N_TOK 8192
#define DM    1024
#define DFF   4096
#define NE    8
#define TOPK  2
#define CAP   1280
#define SROWB 144         // smem row stride bytes (128 data + 16 pad)
#define SSTAGE 55296      // bytes per pipeline stage (384 rows x 144B)
#define NSTAGE 4

// ---------------- scratch ----------------
__device__ __half g_buf[2 * NE * CAP * DM];
__device__ __half g_h  [2 * NE * CAP * DFF];
__device__ __half g_ob [2 * NE * CAP * DM];        // fp16 expert outputs
__device__ __half g_w1t[NE * DFF * DM];
__device__ __half g_w3t[NE * DFF * DM];
__device__ __half g_w2t[NE * DM * DFF];
__device__ float  g_probs[N_TOK * NE];
__device__ int    g_top_idx[N_TOK * TOPK];
__device__ float  g_top_w [N_TOK * TOPK];
__device__ int    g_pos   [N_TOK * TOPK];
__device__ int    g_cnt   [TOPK * NE];

// ---------------- helpers ----------------
__device__ __forceinline__ uint32_t smem_u32(const void* p) {
    uint32_t a;
    asm("{ .reg .u64 t; cvta.to.shared.u64 t, %1; cvt.u32.u64 %0, t; }" : "=r"(a) : "l"(p));
    return a;
}
__device__ __forceinline__ void mma_f16(float* c, const uint32_t* a, uint32_t b0, uint32_t b1) {
    asm volatile(
        "mma.sync.aligned.m16n8k16.row.col.f32.f16.f16.f32 "
        "{%0,%1,%2,%3}, {%4,%5,%6,%7}, {%8,%9}, {%0,%1,%2,%3};"
        : "+f"(c[0]), "+f"(c[1]), "+f"(c[2]), "+f"(c[3])
        : "r"(a[0]), "r"(a[1]), "r"(a[2]), "r"(a[3]), "r"(b0), "r"(b1));
}
__device__ __forceinline__ void ldsm_x4(uint32_t& r0, uint32_t& r1, uint32_t& r2, uint32_t& r3,
                                        uint32_t addr) {
    asm volatile("ldmatrix.sync.aligned.m8n8.x4.shared.b16 {%0,%1,%2,%3}, [%4];"
                 : "=r"(r0), "=r"(r1), "=r"(r2), "=r"(r3) : "r"(addr));
}
__device__ __forceinline__ void cp16(uint32_t s, const void* g) {
    asm volatile("cp.async.cg.shared.global [%0], [%1], 16;" :: "r"(s), "l"(g) : "memory");
}
#define CP_COMMIT() asm volatile("cp.async.commit_group;" ::: "memory")
#define CP_WAIT2()  asm volatile("cp.async.wait_group 2;" ::: "memory")

__device__ __forceinline__ uint32_t h2bits(float a, float b) {
    __half2 h = __floats2half2_rn(a, b);
    return *(uint32_t*)&h;
}

// ---------------- 0. weight convert (fp32 -> fp16) ----------------
__global__ __launch_bounds__(256) void cvt_kernel(const float4* __restrict__ src,
                                                  uint2* __restrict__ dst, int n4) {
    int i = blockIdx.x * blockDim.x + threadIdx.x;
    if (i < n4) {
        float4 v = src[i];
        uint2 o;
        o.x = h2bits(v.x, v.y);
        o.y = h2bits(v.z, v.w);
        dst[i] = o;
    }
}

// ---------------- 1. router (gw staged in smem) ----------------
__global__ __launch_bounds__(256) void router_kernel(const float* __restrict__ x,
                                                     const float* __restrict__ gw) {
    __shared__ float4 sgw[NE * DM / 4];     // 32 KB
    int tid = threadIdx.x;
#pragma unroll
    for (int i = 0; i < NE * DM / 4 / 256; i++)     // 8 per thread
        sgw[i * 256 + tid] = ((const float4*)gw)[i * 256 + tid];
    __syncthreads();

    int warp = (blockIdx.x * blockDim.x + tid) >> 5;
    int lane = tid & 31;
    if (warp >= N_TOK) return;
    const float4* xr = (const float4*)(x + (size_t)warp * DM);
    float acc[NE];
#pragma unroll
    for (int e = 0; e < NE; e++) acc[e] = 0.f;
#pragma unroll
    for (int i = 0; i < DM / 4 / 32; i++) {         // 8 iterations
        int idx = i * 32 + lane;
        float4 xv = xr[idx];
#pragma unroll
        for (int e = 0; e < NE; e++) {
            float4 wv = sgw[e * (DM / 4) + idx];
            acc[e] += xv.x * wv.x + xv.y * wv.y + xv.z * wv.z + xv.w * wv.w;
        }
    }
#pragma unroll
    for (int off = 16; off > 0; off >>= 1)
#pragma unroll
        for (int e = 0; e < NE; e++) acc[e] += __shfl_xor_sync(0xffffffffu, acc[e], off);
    if (lane == 0) {
        float mx = acc[0];
#pragma unroll
        for (int e = 1; e < NE; e++) mx = fmaxf(mx, acc[e]);
        float p[NE], s = 0.f;
#pragma unroll
        for (int e = 0; e < NE; e++) { p[e] = expf(acc[e] - mx); s += p[e]; }
        float inv = 1.f / s;
        int i0 = 0;
#pragma unroll
        for (int e = 1; e < NE; e++) if (p[e] > p[i0]) i0 = e;
        int i1 = (i0 == 0) ? 1 : 0;
#pragma unroll
        for (int e = 0; e < NE; e++) if (e != i0 && e != i1 && p[e] > p[i1]) i1 = e;
#pragma unroll
        for (int e = 0; e < NE; e++) g_probs[warp * NE + e] = p[e] * inv;
        float p0 = p[i0] * inv, p1 = p[i1] * inv;
        float ws = p0 + p1 + 1e-10f;
        g_top_idx[warp * 2 + 0] = i0;  g_top_w[warp * 2 + 0] = p0 / ws;
        g_top_idx[warp * 2 + 1] = i1;  g_top_w[warp * 2 + 1] = p1 / ws;
    }
}

// ---------------- 2. capacity scan ----------------
__global__ __launch_bounds__(256) void scan_kernel() {
    int k = blockIdx.x;
    int t = threadIdx.x;
    const int CH = N_TOK / 256;
    __shared__ int cnt[256][NE];
    int local[NE];
#pragma unroll
    for (int e = 0; e < NE; e++) local[e] = 0;
    for (int i = 0; i < CH; i++) local[g_top_idx[(t * CH + i) * 2 + k]]++;
#pragma unroll
    for (int e = 0; e < NE; e++) cnt[t][e] = local[e];
    __syncthreads();
    if (t < NE) {
        int run = 0;
        for (int i = 0; i < 256; i++) { int v = cnt[i][t]; cnt[i][t] = run; run += v; }
        g_cnt[k * NE + t] = run;
    }
    __syncthreads();
    int off[NE];
#pragma unroll
    for (int e = 0; e < NE; e++) off[e] = cnt[t][e];
    for (int i = 0; i < CH; i++) {
        int tk = (t * CH + i) * 2 + k;
        g_pos[tk] = off[g_top_idx[tk]]++;
    }
}

// ---------------- 3. gather (fp32 -> fp16 at write) ----------------
__global__ __launch_bounds__(256) void gather_kernel(const float* __restrict__ x) {
    int tk = blockIdx.x;
    int pos = g_pos[tk];
    if (pos >= CAP) return;
    int e = g_top_idx[tk];
    int k = tk & 1, t = tk >> 1;
    float4 v = ((const float4*)(x + (size_t)t * DM))[threadIdx.x];
    uint2 o;
    o.x = h2bits(v.x, v.y);
    o.y = h2bits(v.z, v.w);
    uint2* dst = (uint2*)(g_buf + ((size_t)(k * NE + e) * CAP + pos) * DM);
    dst[threadIdx.x] = o;
}

// ---------------- 4. gemm13 fp16 + ldmatrix (unchanged winner) ----------------
__global__ __launch_bounds__(256) void gemm13_mma(const __half* __restrict__ W1,
                                                  const __half* __restrict__ W3) {
    int z = blockIdx.z, e = z & (NE - 1);
    int rows = g_cnt[z]; if (rows > CAP) rows = CAP;
    int m0 = blockIdx.y * 128; if (m0 >= rows) return;
    int n0 = blockIdx.x * 128;

    extern __shared__ char dsm[];
    uint32_t sb = smem_u32(dsm);

    const char* gA  = (const char*)(g_buf + (size_t)z * CAP * DM + (size_t)m0 * DM);
    const char* gB1 = (const char*)(W1 + (size_t)e * DFF * DM + (size_t)n0 * DM);
    const char* gB3 = (const char*)(W3 + (size_t)e * DFF * DM + (size_t)n0 * DM);
    const int GR = DM * 2;

    int tid = threadIdx.x, wid = tid >> 5, lane = tid & 31;
    int wm = wid >> 2, wn = wid & 3;
    int g = lane >> 2, tg = lane & 3;

    uint32_t Aoff = (uint32_t)((wm * 64 + ((lane >> 3) & 1) * 8 + (lane & 7)) * SROWB
                               + (lane >> 4) * 16);
    uint32_t Boff = (uint32_t)(((lane >> 4) * 8 + (lane & 7)) * SROWB
                               + ((lane >> 3) & 1) * 16);

    auto issue = [&](int c) {
        uint32_t st = sb + (uint32_t)(c % NSTAGE) * SSTAGE;
        int kb = c * 128;
#pragma unroll
        for (int i = 0; i < 4; i++) {
            int f = tid + i * 256, r = f >> 3, c4 = f & 7;
            cp16(st + r * SROWB + c4 * 16, gA + (size_t)r * GR + kb + c4 * 16);
        }
#pragma unroll
        for (int i = 0; i < 4; i++) {
            int f = tid + i * 256, r = f >> 3, c4 = f & 7;
            cp16(st + 18432u + r * SROWB + c4 * 16, gB1 + (size_t)r * GR + kb + c4 * 16);
        }
#pragma unroll
        for (int i = 0; i < 4; i++) {
            int f = tid + i * 256, r = f >> 3, c4 = f & 7;
            cp16(st + 36864u + r * SROWB + c4 * 16, gB3 + (size_t)r * GR + kb + c4 * 16);
        }
    };

    float acc1[4][4][4], acc2[4][4][4];
#pragma unroll
    for (int mi = 0; mi < 4; mi++)
#pragma unroll
        for (int ni = 0; ni < 4; ni++)
#pragma unroll
            for (int r = 0; r < 4; r++) { acc1[mi][ni][r] = 0.f; acc2[mi][ni][r] = 0.f; }

    uint32_t af[2][4][4], b1f[2][4][2], b3f[2][4][2];

    auto loadfrag = [&](uint32_t stu, int kk, int buf) {
        uint32_t ka = stu + (uint32_t)(kk * 32);
#pragma unroll
        for (int mi = 0; mi < 4; mi++)
            ldsm_x4(af[buf][mi][0], af[buf][mi][1], af[buf][mi][2], af[buf][mi][3],
                    ka + Aoff + (uint32_t)(mi * 16 * SROWB));
#pragma unroll
        for (int np = 0; np < 2; np++) {
            uint32_t nboff = (uint32_t)((wn * 32 + np * 16) * SROWB);
            ldsm_x4(b1f[buf][2*np][0], b1f[buf][2*np][1], b1f[buf][2*np+1][0], b1f[buf][2*np+1][1],
                    ka + 18432u + Boff + nboff);
            ldsm_x4(b3f[buf][2*np][0], b3f[buf][2*np][1], b3f[buf][2*np+1][0], b3f[buf][2*np+1][1],
                    ka + 36864u + Boff + nboff);
        }
    };

    const int NC = DM / 64;   // 16
    issue(0); CP_COMMIT();
    issue(1); CP_COMMIT();
    issue(2); CP_COMMIT();

    for (int c = 0; c < NC; c++) {
        CP_WAIT2();
        __syncthreads();
        if (c + 3 < NC) issue(c + 3);
        CP_COMMIT();
        uint32_t stu = sb + (uint32_t)(c % NSTAGE) * SSTAGE;
        loadfrag(stu, 0, 0);
#pragma unroll
        for (int kk = 0; kk < 4; kk++) {
            int cur = kk & 1;
            if (kk < 3) loadfrag(stu, kk + 1, cur ^ 1);
#pragma unroll
            for (int ni = 0; ni < 4; ni++) {
#pragma unroll
                for (int mi = 0; mi < 4; mi++)
                    mma_f16(acc1[mi][ni], af[cur][mi], b1f[cur][ni][0], b1f[cur][ni][1]);
#pragma unroll
                for (int mi = 0; mi < 4; mi++)
                    mma_f16(acc2[mi][ni], af[cur][mi], b3f[cur][ni][0], b3f[cur][ni][1]);
            }
        }
    }

    __half* H = g_h + (size_t)z * CAP * DFF;
#pragma unroll
    for (int mi = 0; mi < 4; mi++)
#pragma unroll
        for (int half = 0; half < 2; half++) {
            int m = m0 + wm * 64 + mi * 16 + half * 8 + g;
            if (m < rows) {
#pragma unroll
                for (int ni = 0; ni < 4; ni++) {
                    float v0 = acc1[mi][ni][half * 2 + 0];
                    float v1 = acc1[mi][ni][half * 2 + 1];
                    float o0 = (v0 / (1.f + expf(-v0))) * acc2[mi][ni][half * 2 + 0];
                    float o1 = (v1 / (1.f + expf(-v1))) * acc2[mi][ni][half * 2 + 1];
                    int col = n0 + wn * 32 + ni * 8 + 2 * tg;
                    __half2 hv = __floats2half2_rn(o0, o1);
                    *(__half2*)&H[(size_t)m * DFF + col] = hv;
                }
            }
        }
}

// ---------------- 5. gemm2 fp16 + ldmatrix (fp16 output) ----------------
__global__ __launch_bounds__(256) void gemm2_mma(const __half* __restrict__ W2) {
    int z = blockIdx.z, e = z & (NE - 1);
    int rows = g_cnt[z]; if (rows > CAP) rows = CAP;
    int m0 = blockIdx.y * 128; if (m0 >= rows) return;
    int n0 = blockIdx.x * 256;

    extern __shared__ char dsm[];
    uint32_t sb = smem_u32(dsm);

    const char* gA = (const char*)(g_h + (size_t)z * CAP * DFF + (size_t)m0 * DFF);
    const char* gB = (const char*)(W2 + (size_t)e * DM * DFF + (size_t)n0 * DFF);
    const int GR = DFF * 2;

    int tid = threadIdx.x, wid = tid >> 5, lane = tid & 31;
    int wm = wid >> 2, wn = wid & 3;
    int g = lane >> 2, tg = lane & 3;

    uint32_t Aoff = (uint32_t)((wm * 64 + ((lane >> 3) & 1) * 8 + (lane & 7)) * SROWB
                               + (lane >> 4) * 16);
    uint32_t Boff = (uint32_t)(((lane >> 4) * 8 + (lane & 7)) * SROWB
                               + ((lane >> 3) & 1) * 16);

    auto issue = [&](int c) {
        uint32_t st = sb + (uint32_t)(c % NSTAGE) * SSTAGE;
        int kb = c * 128;
#pragma unroll
        for (int i = 0; i < 4; i++) {
            int f = tid + i * 256, r = f >> 3, c4 = f & 7;
            cp16(st + r * SROWB + c4 * 16, gA + (size_t)r * GR + kb + c4 * 16);
        }
#pragma unroll
        for (int i = 0; i < 8; i++) {
            int f = tid + i * 256, r = f >> 3, c4 = f & 7;
            cp16(st + 18432u + r * SROWB + c4 * 16, gB + (size_t)r * GR + kb + c4 * 16);
        }
    };

    float acc[4][8][4];
#pragma unroll
    for (int mi = 0; mi < 4; mi++)
#pragma unroll
        for (int ni = 0; ni < 8; ni++)
#pragma unroll
            for (int r = 0; r < 4; r++) acc[mi][ni][r] = 0.f;

    uint32_t af[2][4][4], bf[2][8][2];

    auto loadfrag = [&](uint32_t stu, int kk, int buf) {
        uint32_t ka = stu + (uint32_t)(kk * 32);
#pragma unroll
        for (int mi = 0; mi < 4; mi++)
            ldsm_x4(af[buf][mi][0], af[buf][mi][1], af[buf][mi][2], af[buf][mi][3],
                    ka + Aoff + (uint32_t)(mi * 16 * SROWB));
#pragma unroll
        for (int np = 0; np < 4; np++) {
            uint32_t nboff = (uint32_t)((wn * 64 + np * 16) * SROWB);
            ldsm_x4(bf[buf][2*np][0], bf[buf][2*np][1], bf[buf][2*np+1][0], bf[buf][2*np+1][1],
                    ka + 18432u + Boff + nboff);
        }
    };

    const int NC = DFF / 64;  // 64
    issue(0); CP_COMMIT();
    issue(1); CP_COMMIT();
    issue(2); CP_COMMIT();

    for (int c = 0; c < NC; c++) {
        CP_WAIT2();
        __syncthreads();
        if (c + 3 < NC) issue(c + 3);
        CP_COMMIT();
        uint32_t stu = sb + (uint32_t)(c % NSTAGE) * SSTAGE;
        loadfrag(stu, 0, 0);
#pragma unroll
        for (int kk = 0; kk < 4; kk++) {
            int cur = kk & 1;
            if (kk < 3) loadfrag(stu, kk + 1, cur ^ 1);
#pragma unroll
            for (int ni = 0; ni < 8; ni++)
#pragma unroll
                for (int mi = 0; mi < 4; mi++)
                    mma_f16(acc[mi][ni], af[cur][mi], bf[cur][ni][0], bf[cur][ni][1]);
        }
    }

    __half* O = g_ob + (size_t)z * CAP * DM;
#pragma unroll
    for (int mi = 0; mi < 4; mi++)
#pragma unroll
        for (int half = 0; half < 2; half++) {
            int m = m0 + wm * 64 + mi * 16 + half * 8 + g;
            if (m < rows) {
#pragma unroll
                for (int ni = 0; ni < 8; ni++) {
                    int col = n0 + wn * 64 + ni * 8 + 2 * tg;
                    __half2 hv = __floats2half2_rn(acc[mi][ni][half * 2 + 0],
                                                   acc[mi][ni][half * 2 + 1]);
                    *(__half2*)&O[(size_t)m * DM + col] = hv;
                }
            }
        }
}

// ---------------- 6. weighted scatter/combine (fp16 in, fp32 out) ----------------
__global__ __launch_bounds__(256) void scatter_kernel(float* __restrict__ out) {
    int t = blockIdx.x;
    int d4 = threadIdx.x;
    float4 acc = {0.f, 0.f, 0.f, 0.f};
#pragma unroll
    for (int k = 0; k < TOPK; k++) {
        int tk = t * 2 + k;
        int pos = g_pos[tk];
        if (pos < CAP) {
            int e = g_top_idx[tk];
            float w = g_top_w[tk];
            const __half2* src = (const __half2*)(g_ob + ((size_t)(k * NE + e) * CAP + pos) * DM);
            float2 v0 = __half22float2(src[d4 * 2 + 0]);
            float2 v1 = __half22float2(src[d4 * 2 + 1]);
            acc.x += v0.x * w; acc.y += v0.y * w; acc.z += v1.x * w; acc.w += v1.y * w;
        }
    }
    ((float4*)(out + (size_t)t * DM))[d4] = acc;
}

// ---------------- 7. aux loss ----------------
__global__ __launch_bounds__(256) void aux_kernel(float* __restrict__ out, int out_size) {
    __shared__ float red[256];
    __shared__ float Ps[NE];
    int tid = threadIdx.x;
    float loc[NE];
#pragma unroll
    for (int e = 0; e < NE; e++) loc[e] = 0.f;
    for (int i = tid; i < N_TOK; i += 256) {
#pragma unroll
        for (int e = 0; e < NE; e++) loc[e] += g_probs[i * NE + e];
    }
    for (int e = 0; e < NE; e++) {
        red[tid] = loc[e];
        __syncthreads();
        for (int s = 128; s > 0; s >>= 1) {
            if (tid < s) red[tid] += red[tid + s];
            __syncthreads();
        }
        if (tid == 0) Ps[e] = red[0];
        __syncthreads();
    }
    if (tid == 0) {
        float aux = 0.f;
        for (int e = 0; e < NE; e++) {
            float f = (float)(g_cnt[e] + g_cnt[NE + e]) / (float)(N_TOK * TOPK);
            float P = Ps[e] / (float)N_TOK;
            aux += f * P;
        }
        out[out_size - 1] = aux * (float)NE;
    }
}

// ---------------- launch ----------------
extern "C" void kernel_launch(void* const* d_in, const int* in_sizes, int n_in,
                              void* d_out, int out_size) {
    const float* x  = (const float*)d_in[0];
    const float* gw = (const float*)d_in[1];
    const float* w1 = (const float*)d_in[2];
    const float* w2 = (const float*)d_in[3];
    const float* w3 = (const float*)d_in[4];
    float* out = (float*)d_out;

    const int SMEM = NSTAGE * SSTAGE;   // 221184
    cudaFuncSetAttribute(gemm13_mma, cudaFuncAttributeMaxDynamicSharedMemorySize, SMEM);
    cudaFuncSetAttribute(gemm2_mma,  cudaFuncAttributeMaxDynamicSharedMemorySize, SMEM);

    __half* w1t; cudaGetSymbolAddress((void**)&w1t, g_w1t);
    __half* w3t; cudaGetSymbolAddress((void**)&w3t, g_w3t);
    __half* w2t; cudaGetSymbolAddress((void**)&w2t, g_w2t);

    const int N4 = NE * DFF * DM / 4;
    const int CVT_GRID = (N4 + 255) / 256;

    cudaStream_t s2 = 0;
    cudaEvent_t evA = 0, evB = 0, evC = 0, evS = 0, evD = 0;
    bool ok =
        cudaStreamCreateWithFlags(&s2, cudaStreamNonBlocking) == cudaSuccess &&
        cudaEventCreateWithFlags(&evA, cudaEventDisableTiming) == cudaSuccess &&
        cudaEventCreateWithFlags(&evB, cudaEventDisableTiming) == cudaSuccess &&
        cudaEventCreateWithFlags(&evC, cudaEventDisableTiming) == cudaSuccess &&
        cudaEventCreateWithFlags(&evS, cudaEventDisableTiming) == cudaSuccess &&
        cudaEventCreateWithFlags(&evD, cudaEventDisableTiming) == cudaSuccess;
    // objects intentionally leaked (destroying during active capture is illegal;
    // kernel_launch runs only a handful of times).

    if (ok) {
        cudaEventRecord(evA, 0);
        cudaStreamWaitEvent(s2, evA, 0);

        // side stream: weight converts
        cvt_kernel<<<CVT_GRID, 256, 0, s2>>>((const float4*)w1, (uint2*)w1t, N4);
        cvt_kernel<<<CVT_GRID, 256, 0, s2>>>((const float4*)w3, (uint2*)w3t, N4);
        cudaEventRecord(evB, s2);
        cvt_kernel<<<CVT_GRID, 256, 0, s2>>>((const float4*)w2, (uint2*)w2t, N4);
        cudaEventRecord(evC, s2);

        // main: routing pipeline
        router_kernel<<<N_TOK / 8, 256>>>(x, gw);
        scan_kernel<<<2, 256>>>();
        cudaEventRecord(evS, 0);               // g_probs + g_cnt ready
        gather_kernel<<<N_TOK * TOPK, 256>>>(x);

        // side stream: aux loss overlapped with GEMMs
        cudaStreamWaitEvent(s2, evS, 0);
        aux_kernel<<<1, 256, 0, s2>>>(out, out_size);
        cudaEventRecord(evD, s2);

        cudaStreamWaitEvent(0, evB, 0);
        dim3 g1(DFF / 128, CAP / 128, TOPK * NE);
        gemm13_mma<<<g1, 256, SMEM>>>(w1t, w3t);

        cudaStreamWaitEvent(0, evC, 0);
        dim3 g2(DM / 256, CAP / 128, TOPK * NE);
        gemm2_mma<<<g2, 256, SMEM>>>(w2t);

        scatter_kernel<<<N_TOK, 256>>>(out);
        cudaStreamWaitEvent(0, evD, 0);        // join side stream before capture end
    } else {
        cvt_kernel<<<CVT_GRID, 256>>>((const float4*)w1, (uint2*)w1t, N4);
        cvt_kernel<<<CVT_GRID, 256>>>((const float4*)w3, (uint2*)w3t, N4);
        cvt_kernel<<<CVT_GRID, 256>>>((const float4*)w2, (uint2*)w2t, N4);
        router_kernel<<<N_TOK / 8, 256>>>(x, gw);
        scan_kernel<<<2, 256>>>();
        gather_kernel<<<N_TOK * TOPK, 256>>>(x);
        dim3 g1(DFF / 128, CAP / 128, TOPK * NE);
        gemm13_mma<<<g1, 256, SMEM>>>(w1t, w3t);
        dim3 g2(DM / 256, CAP / 128, TOPK * NE);
        gemm2_mma<<<g2, 256, SMEM>>>(w2t);
        scatter_kernel<<<N_TOK, 256>>>(out);
        aux_kernel<<<1, 256>>>(out, out_size);
    }
}

// round 15
// speedup vs baseline: 1.1058x; 1.0111x over previous
#include <cuda_runtime.h>
#include <cuda_fp16.h>
#include <math.h>
#include <stdint.h>

#define N_TOK 8192
#define DM    1024
#define DFF   4096
#define NE    8
#define TOPK  2
#define CAP   1280
#define SROWB 144         // smem row stride bytes (128 data + 16 pad)
#define SSTAGE 55296      // bytes per pipeline stage (384 rows x 144B)
#define NSTAGE 4

// ---------------- scratch ----------------
__device__ __half g_buf[2 * NE * CAP * DM];
__device__ __half g_h  [2 * NE * CAP * DFF];
__device__ __half g_ob [2 * NE * CAP * DM];        // fp16 expert outputs
__device__ __half g_w1t[NE * DFF * DM];
__device__ __half g_w3t[NE * DFF * DM];
__device__ __half g_w2t[NE * DM * DFF];
__device__ float  g_probs[N_TOK * NE];
__device__ int    g_top_idx[N_TOK * TOPK];
__device__ float  g_top_w [N_TOK * TOPK];
__device__ int    g_pos   [N_TOK * TOPK];
__device__ int    g_cnt   [TOPK * NE];

// ---------------- helpers ----------------
__device__ __forceinline__ uint32_t smem_u32(const void* p) {
    uint32_t a;
    asm("{ .reg .u64 t; cvta.to.shared.u64 t, %1; cvt.u32.u64 %0, t; }" : "=r"(a) : "l"(p));
    return a;
}
__device__ __forceinline__ void mma_f16(float* c, const uint32_t* a, uint32_t b0, uint32_t b1) {
    asm volatile(
        "mma.sync.aligned.m16n8k16.row.col.f32.f16.f16.f32 "
        "{%0,%1,%2,%3}, {%4,%5,%6,%7}, {%8,%9}, {%0,%1,%2,%3};"
        : "+f"(c[0]), "+f"(c[1]), "+f"(c[2]), "+f"(c[3])
        : "r"(a[0]), "r"(a[1]), "r"(a[2]), "r"(a[3]), "r"(b0), "r"(b1));
}
__device__ __forceinline__ void ldsm_x4(uint32_t& r0, uint32_t& r1, uint32_t& r2, uint32_t& r3,
                                        uint32_t addr) {
    asm volatile("ldmatrix.sync.aligned.m8n8.x4.shared.b16 {%0,%1,%2,%3}, [%4];"
                 : "=r"(r0), "=r"(r1), "=r"(r2), "=r"(r3) : "r"(addr));
}
__device__ __forceinline__ void cp16(uint32_t s, const void* g) {
    asm volatile("cp.async.cg.shared.global [%0], [%1], 16;" :: "r"(s), "l"(g) : "memory");
}
#define CP_COMMIT() asm volatile("cp.async.commit_group;" ::: "memory")
#define CP_WAIT2()  asm volatile("cp.async.wait_group 2;" ::: "memory")

__device__ __forceinline__ uint32_t h2bits(float a, float b) {
    __half2 h = __floats2half2_rn(a, b);
    return *(uint32_t*)&h;
}

// ---------------- 0. weight convert (fp32 -> fp16) ----------------
__global__ __launch_bounds__(256) void cvt_kernel(const float4* __restrict__ src,
                                                  uint2* __restrict__ dst, int n4) {
    int i = blockIdx.x * blockDim.x + threadIdx.x;
    if (i < n4) {
        float4 v = src[i];
        uint2 o;
        o.x = h2bits(v.x, v.y);
        o.y = h2bits(v.z, v.w);
        dst[i] = o;
    }
}

// ---------------- 1. router (gw staged in smem, 512 threads) ----------------
__global__ __launch_bounds__(512) void router_kernel(const float* __restrict__ x,
                                                     const float* __restrict__ gw) {
    __shared__ float4 sgw[NE * DM / 4];     // 32 KB
    int tid = threadIdx.x;
#pragma unroll
    for (int i = 0; i < NE * DM / 4 / 512; i++)     // 4 per thread
        sgw[i * 512 + tid] = ((const float4*)gw)[i * 512 + tid];
    __syncthreads();

    int warp = (blockIdx.x * 512 + tid) >> 5;
    int lane = tid & 31;
    if (warp >= N_TOK) return;
    const float4* xr = (const float4*)(x + (size_t)warp * DM);
    float acc[NE];
#pragma unroll
    for (int e = 0; e < NE; e++) acc[e] = 0.f;
#pragma unroll
    for (int i = 0; i < DM / 4 / 32; i++) {         // 8 iterations
        int idx = i * 32 + lane;
        float4 xv = xr[idx];
#pragma unroll
        for (int e = 0; e < NE; e++) {
            float4 wv = sgw[e * (DM / 4) + idx];
            acc[e] += xv.x * wv.x + xv.y * wv.y + xv.z * wv.z + xv.w * wv.w;
        }
    }
#pragma unroll
    for (int off = 16; off > 0; off >>= 1)
#pragma unroll
        for (int e = 0; e < NE; e++) acc[e] += __shfl_xor_sync(0xffffffffu, acc[e], off);
    if (lane == 0) {
        float mx = acc[0];
#pragma unroll
        for (int e = 1; e < NE; e++) mx = fmaxf(mx, acc[e]);
        float p[NE], s = 0.f;
#pragma unroll
        for (int e = 0; e < NE; e++) { p[e] = expf(acc[e] - mx); s += p[e]; }
        float inv = 1.f / s;
        int i0 = 0;
#pragma unroll
        for (int e = 1; e < NE; e++) if (p[e] > p[i0]) i0 = e;
        int i1 = (i0 == 0) ? 1 : 0;
#pragma unroll
        for (int e = 0; e < NE; e++) if (e != i0 && e != i1 && p[e] > p[i1]) i1 = e;
#pragma unroll
        for (int e = 0; e < NE; e++) g_probs[warp * NE + e] = p[e] * inv;
        float p0 = p[i0] * inv, p1 = p[i1] * inv;
        float ws = p0 + p1 + 1e-10f;
        g_top_idx[warp * 2 + 0] = i0;  g_top_w[warp * 2 + 0] = p0 / ws;
        g_top_idx[warp * 2 + 1] = i1;  g_top_w[warp * 2 + 1] = p1 / ws;
    }
}

// ---------------- 2. capacity scan ----------------
__global__ __launch_bounds__(256) void scan_kernel() {
    int k = blockIdx.x;
    int t = threadIdx.x;
    const int CH = N_TOK / 256;
    __shared__ int cnt[256][NE];
    int local[NE];
#pragma unroll
    for (int e = 0; e < NE; e++) local[e] = 0;
    for (int i = 0; i < CH; i++) local[g_top_idx[(t * CH + i) * 2 + k]]++;
#pragma unroll
    for (int e = 0; e < NE; e++) cnt[t][e] = local[e];
    __syncthreads();
    if (t < NE) {
        int run = 0;
        for (int i = 0; i < 256; i++) { int v = cnt[i][t]; cnt[i][t] = run; run += v; }
        g_cnt[k * NE + t] = run;
    }
    __syncthreads();
    int off[NE];
#pragma unroll
    for (int e = 0; e < NE; e++) off[e] = cnt[t][e];
    for (int i = 0; i < CH; i++) {
        int tk = (t * CH + i) * 2 + k;
        g_pos[tk] = off[g_top_idx[tk]]++;
    }
}

// ---------------- 3. gather (both k per token, fp32 -> fp16 at write) ----------------
__global__ __launch_bounds__(256) void gather_kernel(const float* __restrict__ x) {
    int t = blockIdx.x;
    float4 v = ((const float4*)(x + (size_t)t * DM))[threadIdx.x];
    uint2 o;
    o.x = h2bits(v.x, v.y);
    o.y = h2bits(v.z, v.w);
#pragma unroll
    for (int k = 0; k < TOPK; k++) {
        int tk = t * 2 + k;
        int pos = g_pos[tk];
        if (pos < CAP) {
            int e = g_top_idx[tk];
            uint2* dst = (uint2*)(g_buf + ((size_t)(k * NE + e) * CAP + pos) * DM);
            dst[threadIdx.x] = o;
        }
    }
}

// ---------------- 4. gemm13 fp16 + ldmatrix (unchanged winner) ----------------
__global__ __launch_bounds__(256) void gemm13_mma(const __half* __restrict__ W1,
                                                  const __half* __restrict__ W3) {
    int z = blockIdx.z, e = z & (NE - 1);
    int rows = g_cnt[z]; if (rows > CAP) rows = CAP;
    int m0 = blockIdx.y * 128; if (m0 >= rows) return;
    int n0 = blockIdx.x * 128;

    extern __shared__ char dsm[];
    uint32_t sb = smem_u32(dsm);

    const char* gA  = (const char*)(g_buf + (size_t)z * CAP * DM + (size_t)m0 * DM);
    const char* gB1 = (const char*)(W1 + (size_t)e * DFF * DM + (size_t)n0 * DM);
    const char* gB3 = (const char*)(W3 + (size_t)e * DFF * DM + (size_t)n0 * DM);
    const int GR = DM * 2;

    int tid = threadIdx.x, wid = tid >> 5, lane = tid & 31;
    int wm = wid >> 2, wn = wid & 3;
    int g = lane >> 2, tg = lane & 3;

    uint32_t Aoff = (uint32_t)((wm * 64 + ((lane >> 3) & 1) * 8 + (lane & 7)) * SROWB
                               + (lane >> 4) * 16);
    uint32_t Boff = (uint32_t)(((lane >> 4) * 8 + (lane & 7)) * SROWB
                               + ((lane >> 3) & 1) * 16);

    auto issue = [&](int c) {
        uint32_t st = sb + (uint32_t)(c % NSTAGE) * SSTAGE;
        int kb = c * 128;
#pragma unroll
        for (int i = 0; i < 4; i++) {
            int f = tid + i * 256, r = f >> 3, c4 = f & 7;
            cp16(st + r * SROWB + c4 * 16, gA + (size_t)r * GR + kb + c4 * 16);
        }
#pragma unroll
        for (int i = 0; i < 4; i++) {
            int f = tid + i * 256, r = f >> 3, c4 = f & 7;
            cp16(st + 18432u + r * SROWB + c4 * 16, gB1 + (size_t)r * GR + kb + c4 * 16);
        }
#pragma unroll
        for (int i = 0; i < 4; i++) {
            int f = tid + i * 256, r = f >> 3, c4 = f & 7;
            cp16(st + 36864u + r * SROWB + c4 * 16, gB3 + (size_t)r * GR + kb + c4 * 16);
        }
    };

    float acc1[4][4][4], acc2[4][4][4];
#pragma unroll
    for (int mi = 0; mi < 4; mi++)
#pragma unroll
        for (int ni = 0; ni < 4; ni++)
#pragma unroll
            for (int r = 0; r < 4; r++) { acc1[mi][ni][r] = 0.f; acc2[mi][ni][r] = 0.f; }

    uint32_t af[2][4][4], b1f[2][4][2], b3f[2][4][2];

    auto loadfrag = [&](uint32_t stu, int kk, int buf) {
        uint32_t ka = stu + (uint32_t)(kk * 32);
#pragma unroll
        for (int mi = 0; mi < 4; mi++)
            ldsm_x4(af[buf][mi][0], af[buf][mi][1], af[buf][mi][2], af[buf][mi][3],
                    ka + Aoff + (uint32_t)(mi * 16 * SROWB));
#pragma unroll
        for (int np = 0; np < 2; np++) {
            uint32_t nboff = (uint32_t)((wn * 32 + np * 16) * SROWB);
            ldsm_x4(b1f[buf][2*np][0], b1f[buf][2*np][1], b1f[buf][2*np+1][0], b1f[buf][2*np+1][1],
                    ka + 18432u + Boff + nboff);
            ldsm_x4(b3f[buf][2*np][0], b3f[buf][2*np][1], b3f[buf][2*np+1][0], b3f[buf][2*np+1][1],
                    ka + 36864u + Boff + nboff);
        }
    };

    const int NC = DM / 64;   // 16
    issue(0); CP_COMMIT();
    issue(1); CP_COMMIT();
    issue(2); CP_COMMIT();

    for (int c = 0; c < NC; c++) {
        CP_WAIT2();
        __syncthreads();
        if (c + 3 < NC) issue(c + 3);
        CP_COMMIT();
        uint32_t stu = sb + (uint32_t)(c % NSTAGE) * SSTAGE;
        loadfrag(stu, 0, 0);
#pragma unroll
        for (int kk = 0; kk < 4; kk++) {
            int cur = kk & 1;
            if (kk < 3) loadfrag(stu, kk + 1, cur ^ 1);
#pragma unroll
            for (int ni = 0; ni < 4; ni++) {
#pragma unroll
                for (int mi = 0; mi < 4; mi++)
                    mma_f16(acc1[mi][ni], af[cur][mi], b1f[cur][ni][0], b1f[cur][ni][1]);
#pragma unroll
                for (int mi = 0; mi < 4; mi++)
                    mma_f16(acc2[mi][ni], af[cur][mi], b3f[cur][ni][0], b3f[cur][ni][1]);
            }
        }
    }

    __half* H = g_h + (size_t)z * CAP * DFF;
#pragma unroll
    for (int mi = 0; mi < 4; mi++)
#pragma unroll
        for (int half = 0; half < 2; half++) {
            int m = m0 + wm * 64 + mi * 16 + half * 8 + g;
            if (m < rows) {
#pragma unroll
                for (int ni = 0; ni < 4; ni++) {
                    float v0 = acc1[mi][ni][half * 2 + 0];
                    float v1 = acc1[mi][ni][half * 2 + 1];
                    float o0 = (v0 / (1.f + expf(-v0))) * acc2[mi][ni][half * 2 + 0];
                    float o1 = (v1 / (1.f + expf(-v1))) * acc2[mi][ni][half * 2 + 1];
                    int col = n0 + wn * 32 + ni * 8 + 2 * tg;
                    __half2 hv = __floats2half2_rn(o0, o1);
                    *(__half2*)&H[(size_t)m * DFF + col] = hv;
                }
            }
        }
}

// ---------------- 5. gemm2 fp16 + ldmatrix (fp16 output) ----------------
__global__ __launch_bounds__(256) void gemm2_mma(const __half* __restrict__ W2) {
    int z = blockIdx.z, e = z & (NE - 1);
    int rows = g_cnt[z]; if (rows > CAP) rows = CAP;
    int m0 = blockIdx.y * 128; if (m0 >= rows) return;
    int n0 = blockIdx.x * 256;

    extern __shared__ char dsm[];
    uint32_t sb = smem_u32(dsm);

    const char* gA = (const char*)(g_h + (size_t)z * CAP * DFF + (size_t)m0 * DFF);
    const char* gB = (const char*)(W2 + (size_t)e * DM * DFF + (size_t)n0 * DFF);
    const int GR = DFF * 2;

    int tid = threadIdx.x, wid = tid >> 5, lane = tid & 31;
    int wm = wid >> 2, wn = wid & 3;
    int g = lane >> 2, tg = lane & 3;

    uint32_t Aoff = (uint32_t)((wm * 64 + ((lane >> 3) & 1) * 8 + (lane & 7)) * SROWB
                               + (lane >> 4) * 16);
    uint32_t Boff = (uint32_t)(((lane >> 4) * 8 + (lane & 7)) * SROWB
                               + ((lane >> 3) & 1) * 16);

    auto issue = [&](int c) {
        uint32_t st = sb + (uint32_t)(c % NSTAGE) * SSTAGE;
        int kb = c * 128;
#pragma unroll
        for (int i = 0; i < 4; i++) {
            int f = tid + i * 256, r = f >> 3, c4 = f & 7;
            cp16(st + r * SROWB + c4 * 16, gA + (size_t)r * GR + kb + c4 * 16);
        }
#pragma unroll
        for (int i = 0; i < 8; i++) {
            int f = tid + i * 256, r = f >> 3, c4 = f & 7;
            cp16(st + 18432u + r * SROWB + c4 * 16, gB + (size_t)r * GR + kb + c4 * 16);
        }
    };

    float acc[4][8][4];
#pragma unroll
    for (int mi = 0; mi < 4; mi++)
#pragma unroll
        for (int ni = 0; ni < 8; ni++)
#pragma unroll
            for (int r = 0; r < 4; r++) acc[mi][ni][r] = 0.f;

    uint32_t af[2][4][4], bf[2][8][2];

    auto loadfrag = [&](uint32_t stu, int kk, int buf) {
        uint32_t ka = stu + (uint32_t)(kk * 32);
#pragma unroll
        for (int mi = 0; mi < 4; mi++)
            ldsm_x4(af[buf][mi][0], af[buf][mi][1], af[buf][mi][2], af[buf][mi][3],
                    ka + Aoff + (uint32_t)(mi * 16 * SROWB));
#pragma unroll
        for (int np = 0; np < 4; np++) {
            uint32_t nboff = (uint32_t)((wn * 64 + np * 16) * SROWB);
            ldsm_x4(bf[buf][2*np][0], bf[buf][2*np][1], bf[buf][2*np+1][0], bf[buf][2*np+1][1],
                    ka + 18432u + Boff + nboff);
        }
    };

    const int NC = DFF / 64;  // 64
    issue(0); CP_COMMIT();
    issue(1); CP_COMMIT();
    issue(2); CP_COMMIT();

    for (int c = 0; c < NC; c++) {
        CP_WAIT2();
        __syncthreads();
        if (c + 3 < NC) issue(c + 3);
        CP_COMMIT();
        uint32_t stu = sb + (uint32_t)(c % NSTAGE) * SSTAGE;
        loadfrag(stu, 0, 0);
#pragma unroll
        for (int kk = 0; kk < 4; kk++) {
            int cur = kk & 1;
            if (kk < 3) loadfrag(stu, kk + 1, cur ^ 1);
#pragma unroll
            for (int ni = 0; ni < 8; ni++)
#pragma unroll
                for (int mi = 0; mi < 4; mi++)
                    mma_f16(acc[mi][ni], af[cur][mi], bf[cur][ni][0], bf[cur][ni][1]);
        }
    }

    __half* O = g_ob + (size_t)z * CAP * DM;
#pragma unroll
    for (int mi = 0; mi < 4; mi++)
#pragma unroll
        for (int half = 0; half < 2; half++) {
            int m = m0 + wm * 64 + mi * 16 + half * 8 + g;
            if (m < rows) {
#pragma unroll
                for (int ni = 0; ni < 8; ni++) {
                    int col = n0 + wn * 64 + ni * 8 + 2 * tg;
                    __half2 hv = __floats2half2_rn(acc[mi][ni][half * 2 + 0],
                                                   acc[mi][ni][half * 2 + 1]);
                    *(__half2*)&O[(size_t)m * DM + col] = hv;
                }
            }
        }
}

// ---------------- 6. weighted scatter/combine (fp16 in, fp32 out) ----------------
__global__ __launch_bounds__(256) void scatter_kernel(float* __restrict__ out) {
    int t = blockIdx.x;
    int d4 = threadIdx.x;
    float4 acc = {0.f, 0.f, 0.f, 0.f};
#pragma unroll
    for (int k = 0; k < TOPK; k++) {
        int tk = t * 2 + k;
        int pos = g_pos[tk];
        if (pos < CAP) {
            int e = g_top_idx[tk];
            float w = g_top_w[tk];
            const __half2* src = (const __half2*)(g_ob + ((size_t)(k * NE + e) * CAP + pos) * DM);
            float2 v0 = __half22float2(src[d4 * 2 + 0]);
            float2 v1 = __half22float2(src[d4 * 2 + 1]);
            acc.x += v0.x * w; acc.y += v0.y * w; acc.z += v1.x * w; acc.w += v1.y * w;
        }
    }
    ((float4*)(out + (size_t)t * DM))[d4] = acc;
}

// ---------------- 7. aux loss ----------------
__global__ __launch_bounds__(256) void aux_kernel(float* __restrict__ out, int out_size) {
    __shared__ float red[256];
    __shared__ float Ps[NE];
    int tid = threadIdx.x;
    float loc[NE];
#pragma unroll
    for (int e = 0; e < NE; e++) loc[e] = 0.f;
    for (int i = tid; i < N_TOK; i += 256) {
#pragma unroll
        for (int e = 0; e < NE; e++) loc[e] += g_probs[i * NE + e];
    }
    for (int e = 0; e < NE; e++) {
        red[tid] = loc[e];
        __syncthreads();
        for (int s = 128; s > 0; s >>= 1) {
            if (tid < s) red[tid] += red[tid + s];
            __syncthreads();
        }
        if (tid == 0) Ps[e] = red[0];
        __syncthreads();
    }
    if (tid == 0) {
        float aux = 0.f;
        for (int e = 0; e < NE; e++) {
            float f = (float)(g_cnt[e] + g_cnt[NE + e]) / (float)(N_TOK * TOPK);
            float P = Ps[e] / (float)N_TOK;
            aux += f * P;
        }
        out[out_size - 1] = aux * (float)NE;
    }
}

// ---------------- launch ----------------
extern "C" void kernel_launch(void* const* d_in, const int* in_sizes, int n_in,
                              void* d_out, int out_size) {
    const float* x  = (const float*)d_in[0];
    const float* gw = (const float*)d_in[1];
    const float* w1 = (const float*)d_in[2];
    const float* w2 = (const float*)d_in[3];
    const float* w3 = (const float*)d_in[4];
    float* out = (float*)d_out;

    const int SMEM = NSTAGE * SSTAGE;   // 221184
    cudaFuncSetAttribute(gemm13_mma, cudaFuncAttributeMaxDynamicSharedMemorySize, SMEM);
    cudaFuncSetAttribute(gemm2_mma,  cudaFuncAttributeMaxDynamicSharedMemorySize, SMEM);

    __half* w1t; cudaGetSymbolAddress((void**)&w1t, g_w1t);
    __half* w3t; cudaGetSymbolAddress((void**)&w3t, g_w3t);
    __half* w2t; cudaGetSymbolAddress((void**)&w2t, g_w2t);

    const int N4 = NE * DFF * DM / 4;
    const int CVT_GRID = (N4 + 255) / 256;

    cudaStream_t s2 = 0;
    cudaEvent_t evA = 0, evB = 0, evC = 0, evS = 0, evD = 0;
    bool ok =
        cudaStreamCreateWithFlags(&s2, cudaStreamNonBlocking) == cudaSuccess &&
        cudaEventCreateWithFlags(&evA, cudaEventDisableTiming) == cudaSuccess &&
        cudaEventCreateWithFlags(&evB, cudaEventDisableTiming) == cudaSuccess &&
        cudaEventCreateWithFlags(&evC, cudaEventDisableTiming) == cudaSuccess &&
        cudaEventCreateWithFlags(&evS, cudaEventDisableTiming) == cudaSuccess &&
        cudaEventCreateWithFlags(&evD, cudaEventDisableTiming) == cudaSuccess;
    // objects intentionally leaked (destroying during active capture is illegal;
    // kernel_launch runs only a handful of times).

    if (ok) {
        cudaEventRecord(evA, 0);
        cudaStreamWaitEvent(s2, evA, 0);

        // side stream: weight converts
        cvt_kernel<<<CVT_GRID, 256, 0, s2>>>((const float4*)w1, (uint2*)w1t, N4);
        cvt_kernel<<<CVT_GRID, 256, 0, s2>>>((const float4*)w3, (uint2*)w3t, N4);
        cudaEventRecord(evB, s2);
        cvt_kernel<<<CVT_GRID, 256, 0, s2>>>((const float4*)w2, (uint2*)w2t, N4);
        cudaEventRecord(evC, s2);

        // main: routing pipeline
        router_kernel<<<N_TOK / 16, 512>>>(x, gw);
        scan_kernel<<<2, 256>>>();
        cudaEventRecord(evS, 0);               // g_probs + g_cnt ready
        gather_kernel<<<N_TOK, 256>>>(x);

        // side stream: aux loss overlapped with GEMMs
        cudaStreamWaitEvent(s2, evS, 0);
        aux_kernel<<<1, 256, 0, s2>>>(out, out_size);
        cudaEventRecord(evD, s2);

        cudaStreamWaitEvent(0, evB, 0);
        dim3 g1(DFF / 128, CAP / 128, TOPK * NE);
        gemm13_mma<<<g1, 256, SMEM>>>(w1t, w3t);

        cudaStreamWaitEvent(0, evC, 0);
        dim3 g2(DM / 256, CAP / 128, TOPK * NE);
        gemm2_mma<<<g2, 256, SMEM>>>(w2t);

        scatter_kernel<<<N_TOK, 256>>>(out);
        cudaStreamWaitEvent(0, evD, 0);        // join side stream before capture end
    } else {
        cvt_kernel<<<CVT_GRID, 256>>>((const float4*)w1, (uint2*)w1t, N4);
        cvt_kernel<<<CVT_GRID, 256>>>((const float4*)w3, (uint2*)w3t, N4);
        cvt_kernel<<<CVT_GRID, 256>>>((const float4*)w2, (uint2*)w2t, N4);
        router_kernel<<<N_TOK / 16, 512>>>(x, gw);
        scan_kernel<<<2, 256>>>();
        gather_kernel<<<N_TOK, 256>>>(x);
        dim3 g1(DFF / 128, CAP / 128, TOPK * NE);
        gemm13_mma<<<g1, 256, SMEM>>>(w1t, w3t);
        dim3 g2(DM / 256, CAP / 128, TOPK * NE);
        gemm2_mma<<<g2, 256, SMEM>>>(w2t);
        scatter_kernel<<<N_TOK, 256>>>(out);
        aux_kernel<<<1, 256>>>(out, out_size);
    }
}